// round 1
// baseline (speedup 1.0000x reference)
#include <cuda_runtime.h>
#include <cstdint>

#define BB 128
#define TT 64
#define II 196
#define DD 512
#define KC 32
// N padded to 224 = 16 lanes * 14 cols (7 f32x2 pairs)

__device__ float g_S[BB * BB];

__device__ __forceinline__ unsigned long long dupf(float v) {
    unsigned int b = __float_as_uint(v);
    return ((unsigned long long)b << 32) | (unsigned long long)b;
}

__global__ __launch_bounds__(128, 3)
void maxsim_kernel(const float* __restrict__ text, const float* __restrict__ img)
{
    // As2[k][t]: duplicated (a,a) f32x2 pair for text value. pitch 66 ull (=132 floats)
    __shared__ unsigned long long As2[KC][66];
    // Bs[k][p]: image pair (i=2p, i=2p+1). pitch 113 ull (=226 floats)
    __shared__ unsigned long long Bs[KC][113];
    __shared__ float red[8];

    const int b1 = blockIdx.x;   // text batch
    const int b2 = blockIdx.y;   // image batch
    const int tid = threadIdx.x;
    const int tx = tid & 15;     // i-group
    const int ty = tid >> 4;     // t-group (0..7), covers t = ty*8 .. ty*8+7

    float* Bsf = (float*)&Bs[0][0];   // pitch 226 floats

    // Zero pad columns i in [196, 226) once (loader never touches them)
    for (int idx = tid; idx < 30 * KC; idx += 128) {
        int k = idx / 30;
        int i = 196 + idx % 30;
        Bsf[k * 226 + i] = 0.0f;
    }

    unsigned long long acc[8][7];
    #pragma unroll
    for (int r = 0; r < 8; r++)
        #pragma unroll
        for (int c = 0; c < 7; c++) acc[r][c] = 0ull;

    const float* tbase = text + (size_t)b1 * TT * DD;
    const float* ibase = img  + (size_t)b2 * II * DD;

    for (int k0 = 0; k0 < DD; k0 += KC) {
        __syncthreads();
        // ---- load text chunk: 64 x 32, store duplicated pairs transposed ----
        #pragma unroll
        for (int q = 0; q < 4; q++) {
            int j  = tid + q * 128;      // 0..511
            int t  = j >> 3;
            int d4 = j & 7;
            float4 v = *(const float4*)(tbase + t * DD + k0 + d4 * 4);
            As2[d4 * 4 + 0][t] = dupf(v.x);
            As2[d4 * 4 + 1][t] = dupf(v.y);
            As2[d4 * 4 + 2][t] = dupf(v.z);
            As2[d4 * 4 + 3][t] = dupf(v.w);
        }
        // ---- load image chunk: 196 x 32, store transposed [k][i] ----
        #pragma unroll
        for (int q = 0; q < 13; q++) {
            int j = tid + q * 128;
            if (j < II * 8) {
                int i  = j >> 3;
                int d4 = j & 7;
                float4 v = *(const float4*)(ibase + i * DD + k0 + d4 * 4);
                Bsf[(d4 * 4 + 0) * 226 + i] = v.x;
                Bsf[(d4 * 4 + 1) * 226 + i] = v.y;
                Bsf[(d4 * 4 + 2) * 226 + i] = v.z;
                Bsf[(d4 * 4 + 3) * 226 + i] = v.w;
            }
        }
        __syncthreads();

        // ---- inner product accumulation via packed f32x2 FMA ----
        #pragma unroll 4
        for (int k = 0; k < KC; k++) {
            unsigned long long a2[8], b2r[7];
            #pragma unroll
            for (int r = 0; r < 8; r++) a2[r] = As2[k][ty * 8 + r];
            #pragma unroll
            for (int c = 0; c < 7; c++) b2r[c] = Bs[k][tx + 16 * c];
            #pragma unroll
            for (int r = 0; r < 8; r++)
                #pragma unroll
                for (int c = 0; c < 7; c++)
                    asm("fma.rn.f32x2 %0, %1, %2, %0;"
                        : "+l"(acc[r][c]) : "l"(a2[r]), "l"(b2r[c]));
        }
    }

    // ---- epilogue: masked max over i, reduce across lanes, mean over t ----
    float tmax[8];
    #pragma unroll
    for (int r = 0; r < 8; r++) {
        float m = -3.0e38f;
        #pragma unroll
        for (int c = 0; c < 7; c++) {
            int i0 = 2 * (tx + 16 * c);
            float lo = __uint_as_float((unsigned)(acc[r][c] & 0xffffffffull));
            float hi = __uint_as_float((unsigned)(acc[r][c] >> 32));
            if (i0     < II) m = fmaxf(m, lo);
            if (i0 + 1 < II) m = fmaxf(m, hi);
        }
        tmax[r] = m;
    }
    // reduce max across the 16 lanes sharing the same ty (xor < 16 stays in half-warp)
    #pragma unroll
    for (int r = 0; r < 8; r++) {
        float m = tmax[r];
        #pragma unroll
        for (int s = 1; s < 16; s <<= 1)
            m = fmaxf(m, __shfl_xor_sync(0xffffffffu, m, s));
        tmax[r] = m;
    }
    if (tx == 0) {
        float s = 0.0f;
        #pragma unroll
        for (int r = 0; r < 8; r++) s += tmax[r];
        red[ty] = s;
    }
    __syncthreads();
    if (tid == 0) {
        float s = 0.0f;
        #pragma unroll
        for (int y = 0; y < 8; y++) s += red[y];
        g_S[b1 * BB + b2] = s * (1.0f / 64.0f);
    }
}

__global__ void loss_kernel(float* __restrict__ out)
{
    __shared__ float part[BB];
    const int b = threadIdx.x;
    const float invT = 1.0f / 0.07f;

    float mr = -3.0e38f, mc = -3.0e38f;
    for (int j = 0; j < BB; j++) {
        float vr = g_S[b * BB + j] * invT;
        float vc = g_S[j * BB + b] * invT;
        mr = fmaxf(mr, vr);
        mc = fmaxf(mc, vc);
    }
    float sr = 0.0f, sc = 0.0f;
    for (int j = 0; j < BB; j++) {
        float vr = g_S[b * BB + j] * invT;
        float vc = g_S[j * BB + b] * invT;
        sr += expf(vr - mr);
        sc += expf(vc - mc);
    }
    float lse_r = mr + logf(sr);
    float lse_c = mc + logf(sc);
    float diag  = g_S[b * BB + b] * invT;

    part[b] = 0.5f * (lse_r + lse_c) - diag;
    __syncthreads();
    if (b == 0) {
        float s = 0.0f;
        for (int j = 0; j < BB; j++) s += part[j];
        out[0] = s * (1.0f / BB);
    }
}

extern "C" void kernel_launch(void* const* d_in, const int* in_sizes, int n_in,
                              void* d_out, int out_size)
{
    const float* a0 = (const float*)d_in[0];
    const float* a1 = (const float*)d_in[1];
    const float* img;
    const float* txt;
    // Identify by element count (image: 128*196*512, text: 128*64*512)
    if (in_sizes[0] == BB * II * DD) { img = a0; txt = a1; }
    else                             { img = a1; txt = a0; }

    dim3 grid(BB, BB);
    maxsim_kernel<<<grid, 128>>>(txt, img);
    loss_kernel<<<1, 128>>>((float*)d_out);
}

// round 3
// speedup vs baseline: 3.6104x; 3.6104x over previous
#include <cuda_runtime.h>
#include <cuda_bf16.h>
#include <cstdint>

#define BB 128
#define TT 64
#define II 196
#define DD 512

// ---------------- scratch (static device globals; no runtime alloc) --------
__device__ __align__(16) __nv_bfloat16 g_thi[BB * TT * DD];
__device__ __align__(16) __nv_bfloat16 g_tlo[BB * TT * DD];
__device__ __align__(16) __nv_bfloat16 g_ihi[BB * II * DD];
__device__ __align__(16) __nv_bfloat16 g_ilo[BB * II * DD];
__device__ float g_S[BB * BB];

// ---------------- stage layout (bytes) --------------------------------------
// K-chunk = 64 cols bf16 = 128 B/row, XOR-swizzled within the 128B row.
#define A_HI 0              // 128 rows x 128B = 16384
#define A_LO 16384
#define B_HI 32768          // 224 rows x 128B = 28672
#define B_LO 61440
#define STAGE_SZ 90112
#define SMEM_TOTAL (2 * STAGE_SZ)   // 180224

// ---------------- PTX helpers (base-target only: sm_80-class) ---------------
__device__ __forceinline__ uint32_t smem_u32(const void* p) {
    uint32_t a;
    asm("{ .reg .u64 t; cvta.to.shared.u64 t, %1; cvt.u32.u64 %0, t; }"
        : "=r"(a) : "l"(p));
    return a;
}

__device__ __forceinline__ void cp16(uint32_t dst, const void* src) {
    asm volatile("cp.async.cg.shared.global [%0], [%1], 16;"
                 :: "r"(dst), "l"(src) : "memory");
}
#define CP_COMMIT() asm volatile("cp.async.commit_group;" ::: "memory")
#define CP_WAIT1()  asm volatile("cp.async.wait_group 1;" ::: "memory")
#define CP_WAIT0()  asm volatile("cp.async.wait_group 0;" ::: "memory")

__device__ __forceinline__ void ldsm4(uint32_t* r, uint32_t addr) {
    asm volatile("ldmatrix.sync.aligned.m8n8.x4.shared.b16 {%0,%1,%2,%3}, [%4];"
                 : "=r"(r[0]), "=r"(r[1]), "=r"(r[2]), "=r"(r[3]) : "r"(addr));
}

__device__ __forceinline__ void mma16816(float* c, const uint32_t* a, const uint32_t* b) {
    asm volatile("mma.sync.aligned.m16n8k16.row.col.f32.bf16.bf16.f32 "
                 "{%0,%1,%2,%3}, {%4,%5,%6,%7}, {%8,%9}, {%0,%1,%2,%3};"
                 : "+f"(c[0]), "+f"(c[1]), "+f"(c[2]), "+f"(c[3])
                 : "r"(a[0]), "r"(a[1]), "r"(a[2]), "r"(a[3]),
                   "r"(b[0]), "r"(b[1]));
}

// swizzled byte offset within a tile: row*128 + (kb ^ ((row&7)<<4))
__device__ __forceinline__ uint32_t swz(int row, uint32_t kb) {
    return (uint32_t)row * 128u + (kb ^ (uint32_t)((row & 7) << 4));
}

// ---------------- split kernel: fp32 -> (hi, lo) bf16 -----------------------
__global__ __launch_bounds__(256)
void split_kernel(const float* __restrict__ src, __nv_bfloat16* __restrict__ hi,
                  __nv_bfloat16* __restrict__ lo, int n4)
{
    int i = blockIdx.x * 256 + threadIdx.x;
    if (i >= n4) return;
    float4 v = reinterpret_cast<const float4*>(src)[i];
    __nv_bfloat16 h0 = __float2bfloat16(v.x);
    __nv_bfloat16 h1 = __float2bfloat16(v.y);
    __nv_bfloat16 h2 = __float2bfloat16(v.z);
    __nv_bfloat16 h3 = __float2bfloat16(v.w);
    __nv_bfloat16 l0 = __float2bfloat16(v.x - __bfloat162float(h0));
    __nv_bfloat16 l1 = __float2bfloat16(v.y - __bfloat162float(h1));
    __nv_bfloat16 l2 = __float2bfloat16(v.z - __bfloat162float(h2));
    __nv_bfloat16 l3 = __float2bfloat16(v.w - __bfloat162float(h3));
    __nv_bfloat162 hA(h0, h1), hB(h2, h3), lA(l0, l1), lB(l2, l3);
    uint2 uh, ul;
    uh.x = *(uint32_t*)&hA; uh.y = *(uint32_t*)&hB;
    ul.x = *(uint32_t*)&lA; ul.y = *(uint32_t*)&lB;
    reinterpret_cast<uint2*>(hi)[i] = uh;
    reinterpret_cast<uint2*>(lo)[i] = ul;
}

// ---------------- stage loader (cp.async) -----------------------------------
__device__ __forceinline__ void issue_stage(uint32_t sb,
    const __nv_bfloat16* Ah, const __nv_bfloat16* Al,
    const __nv_bfloat16* Bh, const __nv_bfloat16* Bl, int k0, int tid)
{
    #pragma unroll
    for (int q = 0; q < 4; q++) {                 // A: 128 rows x 8 segs
        int u = tid + q * 256;
        int row = u >> 3, seg = u & 7;
        uint32_t o = swz(row, seg * 16);
        size_t g = (size_t)row * DD + k0 + seg * 8;
        cp16(sb + A_HI + o, Ah + g);
        cp16(sb + A_LO + o, Al + g);
    }
    #pragma unroll
    for (int q = 0; q < 7; q++) {                 // B: 196 rows x 8 segs = 1568
        int u = tid + q * 256;
        if (u < II * 8) {
            int row = u >> 3, seg = u & 7;
            uint32_t o = swz(row, seg * 16);
            size_t g = (size_t)row * DD + k0 + seg * 8;
            cp16(sb + B_HI + o, Bh + g);
            cp16(sb + B_LO + o, Bl + g);
        }
    }
}

// ---------------- per-chunk HMMA compute ------------------------------------
__device__ __forceinline__ void compute_chunk(uint32_t sb, float* c,
                                              int wr, int wc, int lane)
{
    const int rowA0 = wr * 32 + (lane & 15);
    const uint32_t kAh = (lane & 16) ? 16u : 0u;
    const int rowB0 = wc * 112 + ((lane & 16) ? 8 : 0) + (lane & 7);
    const uint32_t kBh = (lane & 8) ? 16u : 0u;

    #pragma unroll
    for (int s = 0; s < 4; s++) {
        uint32_t aH[8], aL[8];
        #pragma unroll
        for (int mt = 0; mt < 2; mt++) {
            uint32_t o = swz(rowA0 + mt * 16, s * 32 + kAh);
            ldsm4(aH + 4 * mt, sb + A_HI + o);
            ldsm4(aL + 4 * mt, sb + A_LO + o);
        }
        uint32_t bH[28], bL[28];
        #pragma unroll
        for (int p = 0; p < 7; p++) {
            uint32_t o = swz(rowB0 + p * 16, s * 32 + kBh);
            ldsm4(bH + 4 * p, sb + B_HI + o);
            ldsm4(bL + 4 * p, sb + B_LO + o);
        }
        #pragma unroll
        for (int mt = 0; mt < 2; mt++)
            #pragma unroll
            for (int nt = 0; nt < 14; nt++) {
                float* acc = c + (mt * 14 + nt) * 4;
                mma16816(acc, aH + 4 * mt, bH + 2 * nt);
                mma16816(acc, aH + 4 * mt, bL + 2 * nt);
                mma16816(acc, aL + 4 * mt, bH + 2 * nt);
            }
    }
}

// ---------------- main maxsim kernel ----------------------------------------
__global__ __launch_bounds__(256, 1)
void maxsim_mma_kernel()
{
    extern __shared__ __align__(1024) char smem[];
    const uint32_t sb = smem_u32(smem);
    const int tid  = threadIdx.x;
    const int lane = tid & 31;
    const int wid  = tid >> 5;
    const int wr   = wid >> 1;      // 0..3 : M strip of 32
    const int wc   = wid & 1;       // 0..1 : N strip of 112

    const int bx = blockIdx.x;      // text pair -> batches 2bx, 2bx+1
    const int b2 = blockIdx.y;      // image batch
    const __nv_bfloat16* Ah = g_thi + (size_t)bx * (2 * TT * DD);
    const __nv_bfloat16* Al = g_tlo + (size_t)bx * (2 * TT * DD);
    const __nv_bfloat16* Bh = g_ihi + (size_t)b2 * (II * DD);
    const __nv_bfloat16* Bl = g_ilo + (size_t)b2 * (II * DD);

    // zero-fill B pad rows (196..223) in both stages once; loader never writes them
    {
        uint4 z = make_uint4(0, 0, 0, 0);
        for (int u = tid; u < 28 * 8; u += 256) {
            int row = 196 + (u >> 3), seg = u & 7;
            uint32_t o = swz(row, seg * 16);
            *(uint4*)(smem + B_HI + o) = z;
            *(uint4*)(smem + B_LO + o) = z;
            *(uint4*)(smem + STAGE_SZ + B_HI + o) = z;
            *(uint4*)(smem + STAGE_SZ + B_LO + o) = z;
        }
    }
    __syncthreads();

    issue_stage(sb,            Ah, Al, Bh, Bl, 0,  tid); CP_COMMIT();
    issue_stage(sb + STAGE_SZ, Ah, Al, Bh, Bl, 64, tid); CP_COMMIT();

    float c[112];
    #pragma unroll
    for (int i = 0; i < 112; i++) c[i] = 0.0f;

    #pragma unroll 1
    for (int ck = 0; ck < 8; ck++) {
        if (ck < 7) CP_WAIT1(); else CP_WAIT0();
        __syncthreads();
        compute_chunk(sb + (ck & 1) * STAGE_SZ, c, wr, wc, lane);
        __syncthreads();
        if (ck < 6) {
            issue_stage(sb + (ck & 1) * STAGE_SZ, Ah, Al, Bh, Bl, (ck + 2) * 64, tid);
            CP_COMMIT();
        }
    }

    // ---------------- epilogue: masked row-max, then mean over tokens -------
    float* red = (float*)smem;      // [2][128] then [128] scratch — stages done
    #pragma unroll
    for (int mt = 0; mt < 2; mt++) {
        float m0 = -3.0e38f, m1 = -3.0e38f;
        #pragma unroll
        for (int nt = 0; nt < 14; nt++) {
            const float* acc = c + (mt * 14 + nt) * 4;
            int i0 = wc * 112 + nt * 8 + 2 * (lane & 3);
            if (i0 < II)     { m0 = fmaxf(m0, acc[0]); m1 = fmaxf(m1, acc[2]); }
            if (i0 + 1 < II) { m0 = fmaxf(m0, acc[1]); m1 = fmaxf(m1, acc[3]); }
        }
        #pragma unroll
        for (int o = 1; o <= 2; o <<= 1) {
            m0 = fmaxf(m0, __shfl_xor_sync(0xffffffffu, m0, o));
            m1 = fmaxf(m1, __shfl_xor_sync(0xffffffffu, m1, o));
        }
        if ((lane & 3) == 0) {
            int t = wr * 32 + mt * 16 + (lane >> 2);
            red[wc * 128 + t]     = m0;
            red[wc * 128 + t + 8] = m1;
        }
    }
    __syncthreads();
    float* red2 = red + 256;
    if (tid < 128) red2[tid] = fmaxf(red[tid], red[128 + tid]);
    __syncthreads();
    if (wid < 2) {
        float v = red2[wid * 64 + lane] + red2[wid * 64 + 32 + lane];
        #pragma unroll
        for (int o = 16; o >= 1; o >>= 1) v += __shfl_xor_sync(0xffffffffu, v, o);
        if (lane == 0) g_S[(2 * bx + wid) * BB + b2] = v * (1.0f / 64.0f);
    }
}

// ---------------- loss kernel ----------------------------------------------
__global__ __launch_bounds__(256)
void loss_kernel(float* __restrict__ out)
{
    extern __shared__ float sh[];                 // [128][129]
    __shared__ float ws[8];
    const int tid = threadIdx.x;
    const float invT = 1.0f / 0.07f;

    for (int i = tid; i < BB * 32; i += 256) {
        int b = i >> 5, j4 = i & 31;
        float4 v = reinterpret_cast<const float4*>(g_S)[b * 32 + j4];
        float* row = sh + b * 129 + j4 * 4;
        row[0] = v.x; row[1] = v.y; row[2] = v.z; row[3] = v.w;
    }
    __syncthreads();

    const int b = tid & 127;
    const bool isCol = tid >= 128;
    float mx = -3.0e38f;
    #pragma unroll 4
    for (int j = 0; j < BB; j++) {
        float v = (isCol ? sh[j * 129 + b] : sh[b * 129 + j]) * invT;
        mx = fmaxf(mx, v);
    }
    float s = 0.0f;
    #pragma unroll 4
    for (int j = 0; j < BB; j++) {
        float v = (isCol ? sh[j * 129 + b] : sh[b * 129 + j]) * invT;
        s += __expf(v - mx);
    }
    float lse = mx + __logf(s);
    float part = 0.5f * lse;
    if (!isCol) part -= sh[b * 129 + b] * invT;

    #pragma unroll
    for (int o = 16; o >= 1; o >>= 1) part += __shfl_xor_sync(0xffffffffu, part, o);
    if ((tid & 31) == 0) ws[tid >> 5] = part;
    __syncthreads();
    if (tid == 0) {
        float t = 0.0f;
        #pragma unroll
        for (int w = 0; w < 8; w++) t += ws[w];
        out[0] = t * (1.0f / BB);
    }
}

// ---------------- launch ----------------------------------------------------
extern "C" void kernel_launch(void* const* d_in, const int* in_sizes, int n_in,
                              void* d_out, int out_size)
{
    const float* a0 = (const float*)d_in[0];
    const float* a1 = (const float*)d_in[1];
    const float *img, *txt;
    if (in_sizes[0] == BB * II * DD) { img = a0; txt = a1; }
    else                             { img = a1; txt = a0; }

    cudaFuncSetAttribute(maxsim_mma_kernel,
                         cudaFuncAttributeMaxDynamicSharedMemorySize, SMEM_TOTAL);
    cudaFuncSetAttribute(loss_kernel,
                         cudaFuncAttributeMaxDynamicSharedMemorySize, 129 * 128 * 4);

    __nv_bfloat16 *thi, *tlo, *ihi, *ilo;
    cudaGetSymbolAddress((void**)&thi, g_thi);
    cudaGetSymbolAddress((void**)&tlo, g_tlo);
    cudaGetSymbolAddress((void**)&ihi, g_ihi);
    cudaGetSymbolAddress((void**)&ilo, g_ilo);

    const int nt4 = BB * TT * DD / 4;
    const int ni4 = BB * II * DD / 4;
    split_kernel<<<(nt4 + 255) / 256, 256>>>(txt, thi, tlo, nt4);
    split_kernel<<<(ni4 + 255) / 256, 256>>>(img, ihi, ilo, ni4);

    dim3 grid(BB / 2, BB);   // 64 x 128
    maxsim_mma_kernel<<<grid, 256, SMEM_TOTAL>>>();

    loss_kernel<<<1, 256, 129 * 128 * 4>>>((float*)d_out);
}